// round 15
// baseline (speedup 1.0000x reference)
#include <cuda_runtime.h>
#include <cuda_bf16.h>
#include <math.h>
#include <stdint.h>

#define BB 2
#define LL 512
#define HH 768
#define EE 512
#define RR 32768
#define HD2 384
#define BE (BB*EE)
#define NREL (BB*RR)
#define G 256              // persistent grid size
#define TPB 128

typedef __nv_bfloat16 bf16;

// ---------------- static scratch ---------------------------------------------
__device__ __align__(16) bf16 g_repr_hi[BE*HH],   g_repr_lo[BE*HH];
__device__ __align__(16) bf16 g_w1h_hi[HH*HH],    g_w1h_lo[HH*HH];
__device__ __align__(16) bf16 g_w1t_hi[HH*HH],    g_w1t_lo[HH*HH];
__device__ __align__(16) bf16 g_w2h_hi[HD2*HH],   g_w2h_lo[HD2*HH];
__device__ __align__(16) bf16 g_w2t_hi[HD2*HH],   g_w2t_lo[HD2*HH];
__device__ __align__(16) bf16 g_bw_hi[2*HD2*HD2], g_bw_lo[2*HD2*HD2];
__device__ __align__(16) bf16 g_hidh_hi[BE*HH],   g_hidh_lo[BE*HH];
__device__ __align__(16) bf16 g_hidt_hi[BE*HH],   g_hidt_lo[BE*HH];
__device__ __align__(16) bf16 g_tls_hi[BE*HD2],   g_tls_lo[BE*HD2];
__device__ __align__(16) bf16 g_hds_hi[BE*HD2],   g_hds_lo[BE*HD2];
__device__ __align__(16) bf16 g_u_hi[BE*2*HD2],   g_u_lo[BE*2*HD2];
__device__ __align__(16) float g_labh[3*HH];
__device__ __align__(16) float g_labt[3*HH];
__device__ __align__(16) float g_heads[BE*HD2];
__device__ __align__(16) float g_tails[BE*HD2];
__device__ __align__(16) float g_P[BB*EE*EE*2];
__device__ __align__(16) float g_lin4[BE*4];
__device__                float g_partial[G];
__device__ volatile unsigned g_bflag[8];
__device__ unsigned          g_bcnt[8];

__device__ __forceinline__ void split2(float v, bf16& h, bf16& l) {
    h = __float2bfloat16(v);
    l = __float2bfloat16(v - __bfloat162float(h));
}

// ---------------- generation-counter grid barrier (replay-safe) ---------------
__device__ __forceinline__ void gbar(int i) {
    __syncthreads();
    if (threadIdx.x == 0) {
        __threadfence();
        unsigned old = g_bflag[i];
        unsigned my = atomicAdd(&g_bcnt[i], 1u);
        if (my == G - 1) {
            g_bcnt[i] = 0;
            __threadfence();
            g_bflag[i] = old + 1u;
        } else {
            while (g_bflag[i] == old) __nanosleep(64);
        }
    }
    __syncthreads();
}

// ---------------- GEMM tile engine (R10/R14 body, 4 warps, 3-stage) ----------
#define CPA16(saddr, gptr) \
    asm volatile("cp.async.cg.shared.global [%0], [%1], 16;\n" :: "r"(saddr), "l"(gptr))
#define CP_COMMIT() asm volatile("cp.async.commit_group;\n")
#define CP_WAIT2()  asm volatile("cp.async.wait_group 2;\n")

#define MMA_BF16(c, a, b) asm volatile( \
    "mma.sync.aligned.m16n8k16.row.col.f32.bf16.bf16.f32 " \
    "{%0,%1,%2,%3}, {%4,%5,%6,%7}, {%8,%9}, {%0,%1,%2,%3};\n" \
    : "+f"(c[0]), "+f"(c[1]), "+f"(c[2]), "+f"(c[3]) \
    : "r"(a[0]), "r"(a[1]), "r"(a[2]), "r"(a[3]), "r"(b[0]), "r"(b[1]))

#define LDSM4(r0, r1, r2, r3, addr) asm volatile( \
    "ldmatrix.sync.aligned.m8n8.x4.shared.b16 {%0,%1,%2,%3}, [%4];\n" \
    : "=r"(r0), "=r"(r1), "=r"(r2), "=r"(r3) : "r"(addr))

#define STG_BYTES 20480
#define NSTAGE 3
#define GEMM_SMEM (NSTAGE * STG_BYTES)

__device__ __forceinline__ void gemm_tile(
    const bf16* __restrict__ Ahi, const bf16* __restrict__ Alo,
    const bf16* __restrict__ Bhi, const bf16* __restrict__ Blo,
    const float* bias, const float* rowTab, const int* rowLab,
    float* outF, bf16* Chi, bf16* Clo,
    int m0, int n0, int N, int K, bool relu, bf16* sm)
{
    int tid  = threadIdx.x;
    int lane = tid & 31, warp = tid >> 5;
    int wm = warp >> 1, wn = warp & 1;
    int g  = lane >> 2, c2 = (lane & 3) * 2;

    float CH[2][4][4] = {}, CX[2][4][4] = {};

    uint32_t smBase = (uint32_t)__cvta_generic_to_shared(sm);
    const bf16* srcs[4] = {
        Ahi + (size_t)m0 * K, Alo + (size_t)m0 * K,
        Bhi + (size_t)n0 * K, Blo + (size_t)n0 * K };

    uint32_t aRow = wm * 32 + (lane & 15);
    uint32_t aOffHi = smBase + aRow * 80 + ((lane >> 4) & 1) * 16;
    uint32_t bRow0 = wn * 32 + (lane & 7) + ((lane >> 4) & 1) * 8;
    uint32_t bOffHi = smBase + 10240 + bRow0 * 80 + ((lane >> 3) & 1) * 16;

    int KT = K >> 5;

#define ISSUE(s, kt) do {                                            \
        int kbase = (kt) * 32;                                       \
        uint32_t sb = smBase + (s) * STG_BYTES;                      \
        _Pragma("unroll")                                            \
        for (int i = 0; i < 8; i++) {                                \
            int id = i * 128 + tid;                                  \
            int plane = id >> 8;                                     \
            int loc = id & 255;                                      \
            int row = loc >> 2, ck = loc & 3;                        \
            const bf16* gp = srcs[plane] + (size_t)row * K + kbase + ck * 8; \
            CPA16(sb + plane * 5120 + row * 80 + ck * 16, gp);       \
        }                                                            \
        CP_COMMIT();                                                 \
    } while (0)

    ISSUE(0, 0);
    if (1 < KT) ISSUE(1, 1); else CP_COMMIT();

    for (int kt = 0; kt < KT; kt++) {
        if (kt + 2 < KT) ISSUE((kt + 2) % NSTAGE, kt + 2); else CP_COMMIT();
        CP_WAIT2();
        __syncthreads();

        uint32_t stB = (uint32_t)(kt % NSTAGE) * STG_BYTES;
#pragma unroll
        for (int kk = 0; kk < 2; kk++) {
            uint32_t kb = stB + kk * 32;
            uint32_t aH[2][4], aL[2][4], bH[4][2], bL[4][2];
            LDSM4(aH[0][0], aH[0][1], aH[0][2], aH[0][3], aOffHi + kb);
            LDSM4(aH[1][0], aH[1][1], aH[1][2], aH[1][3], aOffHi + kb + 16 * 80);
            LDSM4(aL[0][0], aL[0][1], aL[0][2], aL[0][3], aOffHi + kb + 5120);
            LDSM4(aL[1][0], aL[1][1], aL[1][2], aL[1][3], aOffHi + kb + 5120 + 16 * 80);
            LDSM4(bH[0][0], bH[0][1], bH[1][0], bH[1][1], bOffHi + kb);
            LDSM4(bH[2][0], bH[2][1], bH[3][0], bH[3][1], bOffHi + kb + 16 * 80);
            LDSM4(bL[0][0], bL[0][1], bL[1][0], bL[1][1], bOffHi + kb + 5120);
            LDSM4(bL[2][0], bL[2][1], bL[3][0], bL[3][1], bOffHi + kb + 5120 + 16 * 80);
#pragma unroll
            for (int mt = 0; mt < 2; mt++)
#pragma unroll
                for (int nt = 0; nt < 4; nt++) {
                    MMA_BF16(CH[mt][nt], aH[mt], bH[nt]);
                    MMA_BF16(CX[mt][nt], aH[mt], bL[nt]);
                    MMA_BF16(CX[mt][nt], aL[mt], bH[nt]);
                }
        }
        __syncthreads();
    }
#undef ISSUE

#pragma unroll
    for (int mt = 0; mt < 2; mt++) {
        int rowb = m0 + wm * 32 + mt * 16 + g;
#pragma unroll
        for (int half = 0; half < 2; half++) {
            int rr = rowb + half * 8;
            int lb = rowTab ? __ldg(&rowLab[rr]) : 0;
#pragma unroll
            for (int nt = 0; nt < 4; nt++) {
                int col = n0 + wn * 32 + nt * 8 + c2;
                float v0 = CH[mt][nt][half * 2 + 0] + CX[mt][nt][half * 2 + 0];
                float v1 = CH[mt][nt][half * 2 + 1] + CX[mt][nt][half * 2 + 1];
                if (rowTab) {
                    const float* t = rowTab + (size_t)lb * N + col;
                    v0 += __ldg(t); v1 += __ldg(t + 1);
                } else if (bias) {
                    v0 += __ldg(&bias[col]); v1 += __ldg(&bias[col + 1]);
                }
                if (relu) { v0 = fmaxf(v0, 0.0f); v1 = fmaxf(v1, 0.0f); }
                size_t o = (size_t)rr * N + col;
                if (outF) *(float2*)(outF + o) = make_float2(v0, v1);
                if (Chi) {
                    bf16 h0, l0, h1, l1;
                    split2(v0, h0, l0); split2(v1, h1, l1);
                    *(__nv_bfloat162*)(Chi + o) = __halves2bfloat162(h0, h1);
                    *(__nv_bfloat162*)(Clo + o) = __halves2bfloat162(l0, l1);
                }
            }
        }
    }
}

// ---------------- the persistent megakernel ------------------------------------
struct MegaArgs {
    const float *hidden, *emb;
    const float *hW1, *hb1, *hW2, *hb2, *tW1, *tb1, *tW2, *tb2, *bilW, *linW, *linb;
    const int *ent_start, *ent_label, *rel_head, *rel_tail, *rel_label;
    float* logits_out;
    float* out;
    int write_loss;
};

#define NU_PREP (1024 + 36 + 5 * 1152)

__global__ __launch_bounds__(TPB)
void mega(MegaArgs A) {
    extern __shared__ __align__(16) bf16 sm[];
    int tid = threadIdx.x;
    int bid = blockIdx.x;

    // ---------- phase 0: prep (gather+split, label tables, weight prep) -------
    for (int u = bid; u < NU_PREP; u += G) {
        if (u < 1024) {
            int eg = u, b = eg / EE;
            int idx = __ldg(&A.ent_start[eg]);
            const float* tok = A.hidden + (size_t)(b * LL + idx) * HH;
            size_t base = (size_t)eg * HH;
            for (int i = tid; i < HH; i += TPB) {
                bf16 h, l;
                split2(tok[i], h, l);
                g_repr_hi[base + i] = h;
                g_repr_lo[base + i] = l;
            }
        } else if (u < 1024 + 36) {
            int idx = u - 1024;
            int which = idx / 18, r = idx % 18;
            int l = r / 6, cb = r % 6;
            const float* W1 = which ? A.tW1 : A.hW1;
            const float* b1 = which ? A.tb1 : A.hb1;
            float* tab = which ? g_labt : g_labh;
            int c = cb * TPB + tid;
            float acc = b1[c];
            const float* e = A.emb + (size_t)l * HH;
            for (int k = 0; k < HH; k++)
                acc += e[k] * W1[(size_t)(HH + k) * HH + c];
            tab[l * HH + c] = acc;
        } else {
            int wu = u - 1060;
            int z = wu / 1152, rem = wu % 1152;
            int bx = rem % 24, by = rem / 24;
            const float* src; bf16 *dhi, *dlo; int rows, cols, direct;
            switch (z) {
                case 0: src = A.hW1;  dhi = g_w1h_hi; dlo = g_w1h_lo; rows = HH;      cols = HH;  direct = 0; break;
                case 1: src = A.tW1;  dhi = g_w1t_hi; dlo = g_w1t_lo; rows = HH;      cols = HH;  direct = 0; break;
                case 2: src = A.hW2;  dhi = g_w2h_hi; dlo = g_w2h_lo; rows = HH;      cols = HD2; direct = 0; break;
                case 3: src = A.tW2;  dhi = g_w2t_hi; dlo = g_w2t_lo; rows = HH;      cols = HD2; direct = 0; break;
                default: src = A.bilW; dhi = g_bw_hi; dlo = g_bw_lo;  rows = 2 * HD2; cols = HD2; direct = 1; break;
            }
            int tx = tid & 31, ty = tid >> 5;       // 32 x 4
            int x = bx * 32 + tx;
            if (direct) {
                for (int k = 0; k < 8; k++) {
                    int r = by * 32 + ty + k * 4;
                    if (r < rows && x < cols) {
                        bf16 h, l; split2(src[(size_t)r * cols + x], h, l);
                        dhi[(size_t)r * cols + x] = h;
                        dlo[(size_t)r * cols + x] = l;
                    }
                }
            } else {
                float* tile = (float*)sm;           // [32][33]
                for (int k = 0; k < 8; k++) {
                    int r = by * 32 + ty + k * 4;
                    if (r < rows && x < cols) tile[(ty + k * 4) * 33 + tx] = src[(size_t)r * cols + x];
                }
                __syncthreads();
                int c = by * 32 + tx;
                for (int k = 0; k < 8; k++) {
                    int r = bx * 32 + ty + k * 4;
                    if (r < cols && c < rows) {
                        bf16 h, l; split2(tile[tx * 33 + ty + k * 4], h, l);
                        dhi[(size_t)r * rows + c] = h;
                        dlo[(size_t)r * rows + c] = l;
                    }
                }
                __syncthreads();
            }
        }
    }
    gbar(0);

    // ---------- phase 1: L1 (384 tiles) ---------------------------------------
    for (int t = bid; t < 384; t += G) {
        int z = t / 192, rem = t % 192;
        int bx = rem % 12, by = rem / 12;
        if (z == 0)
            gemm_tile(g_repr_hi, g_repr_lo, g_w1h_hi, g_w1h_lo,
                      nullptr, g_labh, A.ent_label,
                      nullptr, g_hidh_hi, g_hidh_lo,
                      by * 64, bx * 64, HH, HH, true, sm);
        else
            gemm_tile(g_repr_hi, g_repr_lo, g_w1t_hi, g_w1t_lo,
                      nullptr, g_labt, A.ent_label,
                      nullptr, g_hidt_hi, g_hidt_lo,
                      by * 64, bx * 64, HH, HH, true, sm);
    }
    gbar(1);

    // ---------- phase 2: L2 (192 tiles) ---------------------------------------
    for (int t = bid; t < 192; t += G) {
        int z = t / 96, rem = t % 96;
        int bx = rem % 6, by = rem / 6;
        if (z == 0)
            gemm_tile(g_hidh_hi, g_hidh_lo, g_w2h_hi, g_w2h_lo,
                      A.hb2, nullptr, nullptr,
                      g_heads, g_hds_hi, g_hds_lo,
                      by * 64, bx * 64, HD2, HH, true, sm);
        else
            gemm_tile(g_hidt_hi, g_hidt_lo, g_w2t_hi, g_w2t_lo,
                      A.tb2, nullptr, nullptr,
                      g_tails, g_tls_hi, g_tls_lo,
                      by * 64, bx * 64, HD2, HH, true, sm);
    }
    gbar(2);

    // ---------- phase 3: U (192 tiles) + lin dots (64 units) -------------------
    for (int t = bid; t < 256; t += G) {
        if (t < 192) {
            int bx = t % 12, by = t / 12;
            gemm_tile(g_tls_hi, g_tls_lo, g_bw_hi, g_bw_lo,
                      nullptr, nullptr, nullptr,
                      nullptr, g_u_hi, g_u_lo,
                      by * 64, bx * 64, 2 * HD2, HD2, false, sm);
        } else {
            int chunk = t - 192;                   // 0..63, 16 entities each
            int warp = tid >> 5, lane = tid & 31;
            const float* vecs = (warp < 2) ? g_heads : g_tails;
            int o = warp & 1;
            int base = (warp < 2) ? 0 : HD2;
            for (int e = chunk * 16; e < chunk * 16 + 16; e++) {
                const float* v = vecs + (size_t)e * HD2;
                float a = 0.0f;
                for (int d = lane; d < HD2; d += 32)
                    a += v[d] * __ldg(&A.linW[(base + d) * 2 + o]);
#pragma unroll
                for (int off = 16; off > 0; off >>= 1)
                    a += __shfl_down_sync(~0u, a, off);
                if (lane == 0) g_lin4[(size_t)e * 4 + warp] = a;
            }
        }
    }
    gbar(3);

    // ---------- phase 4: P (256 tiles) -----------------------------------------
    {
        int t = bid;                               // exactly one tile per CTA
        int z = t / 128, rem = t % 128;
        int bx = rem % 16, by = rem / 16;
        size_t ho = (size_t)z * EE * HD2;
        size_t uo = (size_t)z * EE * 2 * HD2;
        gemm_tile(g_hds_hi + ho, g_hds_lo + ho, g_u_hi + uo, g_u_lo + uo,
                  nullptr, nullptr, nullptr,
                  g_P + (size_t)z * EE * EE * 2, nullptr, nullptr,
                  by * 64, bx * 64, EE * 2, HD2, false, sm);
    }
    gbar(4);

    // ---------- phase 5: rel gather + logits + CE partials ----------------------
    {
        float* sh = (float*)sm;
        float ce = 0.0f;
#pragma unroll
        for (int p = 0; p < 2; p++) {
            int r = bid * 256 + p * TPB + tid;
            int b = r >> 15;
            int he = A.rel_head[r], te = A.rel_tail[r], lab = A.rel_label[r];
            float2 lhv = *(const float2*)(g_lin4 + (size_t)(b * EE + he) * 4);
            float2 ltv = *(const float2*)(g_lin4 + (size_t)(b * EE + te) * 4 + 2);
            float2 pv = *(const float2*)(g_P + ((size_t)b * EE + he) * (EE * 2) + te * 2);
            float s0 = pv.x + lhv.x + ltv.x + A.linb[0];
            float s1 = pv.y + lhv.y + ltv.y + A.linb[1];
            A.logits_out[(size_t)r * 2 + 0] = s0;
            A.logits_out[(size_t)r * 2 + 1] = s1;
            float m = fmaxf(s0, s1);
            ce += m + logf(expf(s0 - m) + expf(s1 - m)) - (lab ? s1 : s0);
        }
        sh[tid] = ce;
        __syncthreads();
        for (int st = 64; st > 0; st >>= 1) {
            if (tid < st) sh[tid] += sh[tid + st];
            __syncthreads();
        }
        if (tid == 0) g_partial[bid] = sh[0];
    }
    gbar(5);

    // ---------- final: CTA 0 reduces loss ---------------------------------------
    if (bid == 0 && A.write_loss) {
        float* sh = (float*)sm;
        sh[tid] = g_partial[tid] + g_partial[tid + TPB];
        __syncthreads();
        for (int st = 64; st > 0; st >>= 1) {
            if (tid < st) sh[tid] += sh[tid + st];
            __syncthreads();
        }
        if (tid == 0) A.out[0] = sh[0] / (float)RR;
    }
}

// ---------------- launcher -------------------------------------------------------
extern "C" void kernel_launch(void* const* d_in, const int* in_sizes, int n_in,
                              void* d_out, int out_size) {
    MegaArgs A;
    A.hidden    = (const float*)d_in[0];
    A.ent_start = (const int*)  d_in[1];
    A.ent_label = (const int*)  d_in[2];
    A.rel_head  = (const int*)  d_in[3];
    A.rel_tail  = (const int*)  d_in[4];
    A.rel_label = (const int*)  d_in[5];
    A.emb       = (const float*)d_in[6];
    A.hW1 = (const float*)d_in[7];
    A.hb1 = (const float*)d_in[8];
    A.hW2 = (const float*)d_in[9];
    A.hb2 = (const float*)d_in[10];
    A.tW1 = (const float*)d_in[11];
    A.tb1 = (const float*)d_in[12];
    A.tW2 = (const float*)d_in[13];
    A.tb2 = (const float*)d_in[14];
    A.bilW = (const float*)d_in[15];
    A.linW = (const float*)d_in[16];
    A.linb = (const float*)d_in[17];
    float* out = (float*)d_out;

    static bool init = false;
    if (!init) {
        cudaFuncSetAttribute(mega,
            cudaFuncAttributeMaxDynamicSharedMemorySize, GEMM_SMEM);
        init = true;
    }

    int loff = out_size - 2 * NREL;
    if (loff < 0) loff = 0;
    A.logits_out = out + loff;
    A.out = out;
    A.write_loss = (loff > 0) ? 1 : 0;

    mega<<<G, TPB, GEMM_SMEM>>>(A);
}

// round 16
// speedup vs baseline: 1.1886x; 1.1886x over previous
#include <cuda_runtime.h>
#include <cuda_bf16.h>
#include <math.h>
#include <stdint.h>

#define BB 2
#define LL 512
#define HH 768
#define EE 512
#define RR 32768
#define HD2 384
#define BE (BB*EE)
#define NREL (BB*RR)
#define G 444              // persistent grid: 3 CTAs x 148 SMs (full residency)
#define TPB 128

typedef __nv_bfloat16 bf16;

// ---------------- static scratch ---------------------------------------------
__device__ __align__(16) bf16 g_repr_hi[BE*HH],   g_repr_lo[BE*HH];
__device__ __align__(16) bf16 g_w1h_hi[HH*HH],    g_w1h_lo[HH*HH];
__device__ __align__(16) bf16 g_w1t_hi[HH*HH],    g_w1t_lo[HH*HH];
__device__ __align__(16) bf16 g_w2h_hi[HD2*HH],   g_w2h_lo[HD2*HH];
__device__ __align__(16) bf16 g_w2t_hi[HD2*HH],   g_w2t_lo[HD2*HH];
__device__ __align__(16) bf16 g_bw_hi[2*HD2*HD2], g_bw_lo[2*HD2*HD2];
__device__ __align__(16) bf16 g_hidh_hi[BE*HH],   g_hidh_lo[BE*HH];
__device__ __align__(16) bf16 g_hidt_hi[BE*HH],   g_hidt_lo[BE*HH];
__device__ __align__(16) bf16 g_tls_hi[BE*HD2],   g_tls_lo[BE*HD2];
__device__ __align__(16) bf16 g_hds_hi[BE*HD2],   g_hds_lo[BE*HD2];
__device__ __align__(16) bf16 g_u_hi[BE*2*HD2],   g_u_lo[BE*2*HD2];
__device__ __align__(16) float g_labh[3*HH];
__device__ __align__(16) float g_labt[3*HH];
__device__ __align__(16) float g_heads[BE*HD2];
__device__ __align__(16) float g_tails[BE*HD2];
__device__ __align__(16) float g_P[BB*EE*EE*2];
__device__ __align__(16) float g_lin4[BE*4];
__device__                float g_partial[G];
__device__ volatile unsigned g_bflag[8];
__device__ unsigned          g_bcnt[8];

__device__ __forceinline__ void split2(float v, bf16& h, bf16& l) {
    h = __float2bfloat16(v);
    l = __float2bfloat16(v - __bfloat162float(h));
}

// ---------------- generation-counter grid barrier (replay-safe) ---------------
__device__ __forceinline__ void gbar(int i) {
    __syncthreads();
    if (threadIdx.x == 0) {
        __threadfence();
        unsigned old = g_bflag[i];
        unsigned my = atomicAdd(&g_bcnt[i], 1u);
        if (my == G - 1) {
            g_bcnt[i] = 0;
            __threadfence();
            g_bflag[i] = old + 1u;
        } else {
            while (g_bflag[i] == old) __nanosleep(32);
        }
    }
    __syncthreads();
}

// ---------------- GEMM tile engine (R10/R14 body, 4 warps, 3-stage) ----------
#define CPA16(saddr, gptr) \
    asm volatile("cp.async.cg.shared.global [%0], [%1], 16;\n" :: "r"(saddr), "l"(gptr))
#define CP_COMMIT() asm volatile("cp.async.commit_group;\n")
#define CP_WAIT2()  asm volatile("cp.async.wait_group 2;\n")

#define MMA_BF16(c, a, b) asm volatile( \
    "mma.sync.aligned.m16n8k16.row.col.f32.bf16.bf16.f32 " \
    "{%0,%1,%2,%3}, {%4,%5,%6,%7}, {%8,%9}, {%0,%1,%2,%3};\n" \
    : "+f"(c[0]), "+f"(c[1]), "+f"(c[2]), "+f"(c[3]) \
    : "r"(a[0]), "r"(a[1]), "r"(a[2]), "r"(a[3]), "r"(b[0]), "r"(b[1]))

#define LDSM4(r0, r1, r2, r3, addr) asm volatile( \
    "ldmatrix.sync.aligned.m8n8.x4.shared.b16 {%0,%1,%2,%3}, [%4];\n" \
    : "=r"(r0), "=r"(r1), "=r"(r2), "=r"(r3) : "r"(addr))

#define STG_BYTES 20480
#define NSTAGE 3
#define GEMM_SMEM (NSTAGE * STG_BYTES)

__device__ __forceinline__ void gemm_tile(
    const bf16* __restrict__ Ahi, const bf16* __restrict__ Alo,
    const bf16* __restrict__ Bhi, const bf16* __restrict__ Blo,
    const float* bias, const float* rowTab, const int* rowLab,
    float* outF, bf16* Chi, bf16* Clo,
    int m0, int n0, int N, int K, bool relu, bf16* sm)
{
    int tid  = threadIdx.x;
    int lane = tid & 31, warp = tid >> 5;
    int wm = warp >> 1, wn = warp & 1;
    int g  = lane >> 2, c2 = (lane & 3) * 2;

    float CH[2][4][4] = {}, CX[2][4][4] = {};

    uint32_t smBase = (uint32_t)__cvta_generic_to_shared(sm);
    const bf16* srcs[4] = {
        Ahi + (size_t)m0 * K, Alo + (size_t)m0 * K,
        Bhi + (size_t)n0 * K, Blo + (size_t)n0 * K };

    uint32_t aRow = wm * 32 + (lane & 15);
    uint32_t aOffHi = smBase + aRow * 80 + ((lane >> 4) & 1) * 16;
    uint32_t bRow0 = wn * 32 + (lane & 7) + ((lane >> 4) & 1) * 8;
    uint32_t bOffHi = smBase + 10240 + bRow0 * 80 + ((lane >> 3) & 1) * 16;

    int KT = K >> 5;

#define ISSUE(s, kt) do {                                            \
        int kbase = (kt) * 32;                                       \
        uint32_t sb = smBase + (s) * STG_BYTES;                      \
        _Pragma("unroll")                                            \
        for (int i = 0; i < 8; i++) {                                \
            int id = i * 128 + tid;                                  \
            int plane = id >> 8;                                     \
            int loc = id & 255;                                      \
            int row = loc >> 2, ck = loc & 3;                        \
            const bf16* gp = srcs[plane] + (size_t)row * K + kbase + ck * 8; \
            CPA16(sb + plane * 5120 + row * 80 + ck * 16, gp);       \
        }                                                            \
        CP_COMMIT();                                                 \
    } while (0)

    ISSUE(0, 0);
    if (1 < KT) ISSUE(1, 1); else CP_COMMIT();

    for (int kt = 0; kt < KT; kt++) {
        if (kt + 2 < KT) ISSUE((kt + 2) % NSTAGE, kt + 2); else CP_COMMIT();
        CP_WAIT2();
        __syncthreads();

        uint32_t stB = (uint32_t)(kt % NSTAGE) * STG_BYTES;
#pragma unroll
        for (int kk = 0; kk < 2; kk++) {
            uint32_t kb = stB + kk * 32;
            uint32_t aH[2][4], aL[2][4], bH[4][2], bL[4][2];
            LDSM4(aH[0][0], aH[0][1], aH[0][2], aH[0][3], aOffHi + kb);
            LDSM4(aH[1][0], aH[1][1], aH[1][2], aH[1][3], aOffHi + kb + 16 * 80);
            LDSM4(aL[0][0], aL[0][1], aL[0][2], aL[0][3], aOffHi + kb + 5120);
            LDSM4(aL[1][0], aL[1][1], aL[1][2], aL[1][3], aOffHi + kb + 5120 + 16 * 80);
            LDSM4(bH[0][0], bH[0][1], bH[1][0], bH[1][1], bOffHi + kb);
            LDSM4(bH[2][0], bH[2][1], bH[3][0], bH[3][1], bOffHi + kb + 16 * 80);
            LDSM4(bL[0][0], bL[0][1], bL[1][0], bL[1][1], bOffHi + kb + 5120);
            LDSM4(bL[2][0], bL[2][1], bL[3][0], bL[3][1], bOffHi + kb + 5120 + 16 * 80);
#pragma unroll
            for (int mt = 0; mt < 2; mt++)
#pragma unroll
                for (int nt = 0; nt < 4; nt++) {
                    MMA_BF16(CH[mt][nt], aH[mt], bH[nt]);
                    MMA_BF16(CX[mt][nt], aH[mt], bL[nt]);
                    MMA_BF16(CX[mt][nt], aL[mt], bH[nt]);
                }
        }
        __syncthreads();
    }
#undef ISSUE

#pragma unroll
    for (int mt = 0; mt < 2; mt++) {
        int rowb = m0 + wm * 32 + mt * 16 + g;
#pragma unroll
        for (int half = 0; half < 2; half++) {
            int rr = rowb + half * 8;
            int lb = rowTab ? __ldg(&rowLab[rr]) : 0;
#pragma unroll
            for (int nt = 0; nt < 4; nt++) {
                int col = n0 + wn * 32 + nt * 8 + c2;
                float v0 = CH[mt][nt][half * 2 + 0] + CX[mt][nt][half * 2 + 0];
                float v1 = CH[mt][nt][half * 2 + 1] + CX[mt][nt][half * 2 + 1];
                if (rowTab) {
                    const float* t = rowTab + (size_t)lb * N + col;
                    v0 += __ldg(t); v1 += __ldg(t + 1);
                } else if (bias) {
                    v0 += __ldg(&bias[col]); v1 += __ldg(&bias[col + 1]);
                }
                if (relu) { v0 = fmaxf(v0, 0.0f); v1 = fmaxf(v1, 0.0f); }
                size_t o = (size_t)rr * N + col;
                if (outF) *(float2*)(outF + o) = make_float2(v0, v1);
                if (Chi) {
                    bf16 h0, l0, h1, l1;
                    split2(v0, h0, l0); split2(v1, h1, l1);
                    *(__nv_bfloat162*)(Chi + o) = __halves2bfloat162(h0, h1);
                    *(__nv_bfloat162*)(Clo + o) = __halves2bfloat162(l0, l1);
                }
            }
        }
    }
}

// ---------------- the persistent megakernel ------------------------------------
struct MegaArgs {
    const float *hidden, *emb;
    const float *hW1, *hb1, *hW2, *hb2, *tW1, *tb1, *tW2, *tb2, *bilW, *linW, *linb;
    const int *ent_start, *ent_label, *rel_head, *rel_tail, *rel_label;
    float* logits_out;
    float* out;
    int write_loss;
};

#define NU_PREP (1024 + 36 + 5 * 1152)

__global__ __launch_bounds__(TPB, 3)
void mega(MegaArgs A) {
    extern __shared__ __align__(16) bf16 sm[];
    int tid = threadIdx.x;
    int bid = blockIdx.x;

    // ---------- phase 0: prep (gather+split, label tables, weight prep) -------
    for (int u = bid; u < NU_PREP; u += G) {
        if (u < 1024) {
            int eg = u, b = eg / EE;
            int idx = __ldg(&A.ent_start[eg]);
            const float* tok = A.hidden + (size_t)(b * LL + idx) * HH;
            size_t base = (size_t)eg * HH;
            for (int i = tid; i < HH; i += TPB) {
                bf16 h, l;
                split2(tok[i], h, l);
                g_repr_hi[base + i] = h;
                g_repr_lo[base + i] = l;
            }
        } else if (u < 1024 + 36) {
            int idx = u - 1024;
            int which = idx / 18, r = idx % 18;
            int l = r / 6, cb = r % 6;
            const float* W1 = which ? A.tW1 : A.hW1;
            const float* b1 = which ? A.tb1 : A.hb1;
            float* tab = which ? g_labt : g_labh;
            int c = cb * TPB + tid;
            float acc = b1[c];
            const float* e = A.emb + (size_t)l * HH;
            for (int k = 0; k < HH; k++)
                acc += e[k] * W1[(size_t)(HH + k) * HH + c];
            tab[l * HH + c] = acc;
        } else {
            int wu = u - 1060;
            int z = wu / 1152, rem = wu % 1152;
            int bx = rem % 24, by = rem / 24;
            const float* src; bf16 *dhi, *dlo; int rows, cols, direct;
            switch (z) {
                case 0: src = A.hW1;  dhi = g_w1h_hi; dlo = g_w1h_lo; rows = HH;      cols = HH;  direct = 0; break;
                case 1: src = A.tW1;  dhi = g_w1t_hi; dlo = g_w1t_lo; rows = HH;      cols = HH;  direct = 0; break;
                case 2: src = A.hW2;  dhi = g_w2h_hi; dlo = g_w2h_lo; rows = HH;      cols = HD2; direct = 0; break;
                case 3: src = A.tW2;  dhi = g_w2t_hi; dlo = g_w2t_lo; rows = HH;      cols = HD2; direct = 0; break;
                default: src = A.bilW; dhi = g_bw_hi; dlo = g_bw_lo;  rows = 2 * HD2; cols = HD2; direct = 1; break;
            }
            int tx = tid & 31, ty = tid >> 5;       // 32 x 4
            int x = bx * 32 + tx;
            if (direct) {
                for (int k = 0; k < 8; k++) {
                    int r = by * 32 + ty + k * 4;
                    if (r < rows && x < cols) {
                        bf16 h, l; split2(src[(size_t)r * cols + x], h, l);
                        dhi[(size_t)r * cols + x] = h;
                        dlo[(size_t)r * cols + x] = l;
                    }
                }
            } else {
                float* tile = (float*)sm;           // [32][33]
                for (int k = 0; k < 8; k++) {
                    int r = by * 32 + ty + k * 4;
                    if (r < rows && x < cols) tile[(ty + k * 4) * 33 + tx] = src[(size_t)r * cols + x];
                }
                __syncthreads();
                int c = by * 32 + tx;
                for (int k = 0; k < 8; k++) {
                    int r = bx * 32 + ty + k * 4;
                    if (r < cols && c < rows) {
                        bf16 h, l; split2(tile[tx * 33 + ty + k * 4], h, l);
                        dhi[(size_t)r * rows + c] = h;
                        dlo[(size_t)r * rows + c] = l;
                    }
                }
                __syncthreads();
            }
        }
    }
    gbar(0);

    // ---------- phase 1: L1 (384 tiles, one wave) ------------------------------
    for (int t = bid; t < 384; t += G) {
        int z = t / 192, rem = t % 192;
        int bx = rem % 12, by = rem / 12;
        if (z == 0)
            gemm_tile(g_repr_hi, g_repr_lo, g_w1h_hi, g_w1h_lo,
                      nullptr, g_labh, A.ent_label,
                      nullptr, g_hidh_hi, g_hidh_lo,
                      by * 64, bx * 64, HH, HH, true, sm);
        else
            gemm_tile(g_repr_hi, g_repr_lo, g_w1t_hi, g_w1t_lo,
                      nullptr, g_labt, A.ent_label,
                      nullptr, g_hidt_hi, g_hidt_lo,
                      by * 64, bx * 64, HH, HH, true, sm);
    }
    gbar(1);

    // ---------- phase 2: L2 (192 tiles) ----------------------------------------
    for (int t = bid; t < 192; t += G) {
        int z = t / 96, rem = t % 96;
        int bx = rem % 6, by = rem / 6;
        if (z == 0)
            gemm_tile(g_hidh_hi, g_hidh_lo, g_w2h_hi, g_w2h_lo,
                      A.hb2, nullptr, nullptr,
                      g_heads, g_hds_hi, g_hds_lo,
                      by * 64, bx * 64, HD2, HH, true, sm);
        else
            gemm_tile(g_hidt_hi, g_hidt_lo, g_w2t_hi, g_w2t_lo,
                      A.tb2, nullptr, nullptr,
                      g_tails, g_tls_hi, g_tls_lo,
                      by * 64, bx * 64, HD2, HH, true, sm);
    }
    gbar(2);

    // ---------- phase 3: U (192 tiles) + lin dots (64 units) --------------------
    for (int t = bid; t < 256; t += G) {
        if (t < 192) {
            int bx = t % 12, by = t / 12;
            gemm_tile(g_tls_hi, g_tls_lo, g_bw_hi, g_bw_lo,
                      nullptr, nullptr, nullptr,
                      nullptr, g_u_hi, g_u_lo,
                      by * 64, bx * 64, 2 * HD2, HD2, false, sm);
        } else {
            int chunk = t - 192;                   // 0..63, 16 entities each
            int warp = tid >> 5, lane = tid & 31;
            const float* vecs = (warp < 2) ? g_heads : g_tails;
            int o = warp & 1;
            int base = (warp < 2) ? 0 : HD2;
            for (int e = chunk * 16; e < chunk * 16 + 16; e++) {
                const float* v = vecs + (size_t)e * HD2;
                float a = 0.0f;
                for (int d = lane; d < HD2; d += 32)
                    a += v[d] * __ldg(&A.linW[(base + d) * 2 + o]);
#pragma unroll
                for (int off = 16; off > 0; off >>= 1)
                    a += __shfl_down_sync(~0u, a, off);
                if (lane == 0) g_lin4[(size_t)e * 4 + warp] = a;
            }
        }
    }
    gbar(3);

    // ---------- phase 4: P (256 tiles) ------------------------------------------
    for (int t = bid; t < 256; t += G) {
        int z = t / 128, rem = t % 128;
        int bx = rem % 16, by = rem / 16;
        size_t ho = (size_t)z * EE * HD2;
        size_t uo = (size_t)z * EE * 2 * HD2;
        gemm_tile(g_hds_hi + ho, g_hds_lo + ho, g_u_hi + uo, g_u_lo + uo,
                  nullptr, nullptr, nullptr,
                  g_P + (size_t)z * EE * EE * 2, nullptr, nullptr,
                  by * 64, bx * 64, EE * 2, HD2, false, sm);
    }
    gbar(4);

    // ---------- phase 5: rel gather + logits + CE partials -----------------------
    {
        float* sh = (float*)sm;
        float ce = 0.0f;
        for (int r = bid * TPB + tid; r < NREL; r += G * TPB) {
            int b = r >> 15;
            int he = A.rel_head[r], te = A.rel_tail[r], lab = A.rel_label[r];
            float2 lhv = *(const float2*)(g_lin4 + (size_t)(b * EE + he) * 4);
            float2 ltv = *(const float2*)(g_lin4 + (size_t)(b * EE + te) * 4 + 2);
            float2 pv = *(const float2*)(g_P + ((size_t)b * EE + he) * (EE * 2) + te * 2);
            float s0 = pv.x + lhv.x + ltv.x + A.linb[0];
            float s1 = pv.y + lhv.y + ltv.y + A.linb[1];
            A.logits_out[(size_t)r * 2 + 0] = s0;
            A.logits_out[(size_t)r * 2 + 1] = s1;
            float m = fmaxf(s0, s1);
            ce += m + logf(expf(s0 - m) + expf(s1 - m)) - (lab ? s1 : s0);
        }
        sh[tid] = ce;
        __syncthreads();
        for (int st = 64; st > 0; st >>= 1) {
            if (tid < st) sh[tid] += sh[tid + st];
            __syncthreads();
        }
        if (tid == 0) g_partial[bid] = sh[0];
    }
    gbar(5);

    // ---------- final: CTA 0 reduces loss ----------------------------------------
    if (bid == 0 && A.write_loss) {
        float* sh = (float*)sm;
        float acc = 0.0f;
        for (int i = tid; i < G; i += TPB) acc += g_partial[i];
        sh[tid] = acc;
        __syncthreads();
        for (int st = 64; st > 0; st >>= 1) {
            if (tid < st) sh[tid] += sh[tid + st];
            __syncthreads();
        }
        if (tid == 0) A.out[0] = sh[0] / (float)RR;
    }
}

// ---------------- launcher -------------------------------------------------------
extern "C" void kernel_launch(void* const* d_in, const int* in_sizes, int n_in,
                              void* d_out, int out_size) {
    MegaArgs A;
    A.hidden    = (const float*)d_in[0];
    A.ent_start = (const int*)  d_in[1];
    A.ent_label = (const int*)  d_in[2];
    A.rel_head  = (const int*)  d_in[3];
    A.rel_tail  = (const int*)  d_in[4];
    A.rel_label = (const int*)  d_in[5];
    A.emb       = (const float*)d_in[6];
    A.hW1 = (const float*)d_in[7];
    A.hb1 = (const float*)d_in[8];
    A.hW2 = (const float*)d_in[9];
    A.hb2 = (const float*)d_in[10];
    A.tW1 = (const float*)d_in[11];
    A.tb1 = (const float*)d_in[12];
    A.tW2 = (const float*)d_in[13];
    A.tb2 = (const float*)d_in[14];
    A.bilW = (const float*)d_in[15];
    A.linW = (const float*)d_in[16];
    A.linb = (const float*)d_in[17];
    float* out = (float*)d_out;

    static bool init = false;
    if (!init) {
        cudaFuncSetAttribute(mega,
            cudaFuncAttributeMaxDynamicSharedMemorySize, GEMM_SMEM);
        init = true;
    }

    int loff = out_size - 2 * NREL;
    if (loff < 0) loff = 0;
    A.logits_out = out + loff;
    A.out = out;
    A.write_loss = (loff > 0) ? 1 : 0;

    mega<<<G, TPB, GEMM_SMEM>>>(A);
}